// round 13
// baseline (speedup 1.0000x reference)
#include <cuda_runtime.h>
#include <cuda_fp16.h>
#include <cstdint>

// Problem shape (fixed by the dataset)
#define M_TOT   64
#define K_TOT   4096
#define O_TOT   11008
#define GROUP   128
#define NGRP    (K_TOT / GROUP)        // 32
#define GPACK   ((NGRP + 7) / 8)       // 4

// Tiling
#define BN      64          // outputs per block
#define BK      128         // K chunk = one quant group
#define KSPLIT  2           // grid (172, 2) = 344 blocks -> one wave at 3 blocks/SM
#define NCHS    (K_TOT / BK / KSPLIT)  // 16 chunks per block
#define PADH    8
#define XSTR    (BK + PADH)            // 136 halfs row stride (272 B)
#define NTHREADS 256

#define TILE_HALFS   (64 * XSTR)           // one 64-row tile
#define TILE_BYTES   (TILE_HALFS * 2)      // 17408 B
#define SMEM_BYTES   (4 * TILE_BYTES)      // xs[2] + ws[2] = 69632 B

// fp16 copy of x, produced once per launch
__device__ __half g_xh[M_TOT * K_TOT];

#define ZERO_F4   (M_TOT * O_TOT / 4)
#define CVT_F4    (M_TOT * K_TOT / 4)
#define PRO_TOT   (ZERO_F4 + CVT_F4)

__global__ __launch_bounds__(512) void prologue_kernel(const float* __restrict__ x,
                                                       float* __restrict__ out)
{
    int idx = blockIdx.x * blockDim.x + threadIdx.x;
    if (idx < ZERO_F4) {
        ((float4*)out)[idx] = make_float4(0.f, 0.f, 0.f, 0.f);
    } else if (idx < PRO_TOT) {
        int i = idx - ZERO_F4;
        float4 v = ((const float4*)x)[i];
        __half2* dst = (__half2*)g_xh;
        dst[i * 2]     = __floats2half2_rn(v.x, v.y);
        dst[i * 2 + 1] = __floats2half2_rn(v.z, v.w);
    }
}

#define CP_ASYNC16(dst_u32, src_ptr) \
    asm volatile("cp.async.cg.shared.global [%0], [%1], 16;\n" :: "r"(dst_u32), "l"(src_ptr))
#define CP_COMMIT() asm volatile("cp.async.commit_group;\n" ::: "memory")
#define CP_WAIT0()  asm volatile("cp.async.wait_group 0;\n" ::: "memory")

#define LDSM_X4(r0, r1, r2, r3, addr) \
    asm volatile("ldmatrix.sync.aligned.m8n8.x4.shared.b16 {%0,%1,%2,%3}, [%4];\n" \
                 : "=r"(r0), "=r"(r1), "=r"(r2), "=r"(r3) : "r"(addr))
#define LDSM_X2(r0, r1, addr) \
    asm volatile("ldmatrix.sync.aligned.m8n8.x2.shared.b16 {%0,%1}, [%2];\n" \
                 : "=r"(r0), "=r"(r1) : "r"(addr))

__global__ __launch_bounds__(NTHREADS)
void w4a16_mma_kernel(const int*   __restrict__ qw,
                      const int*   __restrict__ qz,
                      const float* __restrict__ sc,
                      float*       __restrict__ out)
{
    extern __shared__ __half smem[];
    __half (*xs)[64][XSTR] = (__half (*)[64][XSTR])smem;                    // [2][64][136]
    __half (*ws)[64][XSTR] = (__half (*)[64][XSTR])(smem + 2 * TILE_HALFS); // [2][64][136]

    const int tid  = threadIdx.x;
    const int warp = tid >> 5;
    const int lane = tid & 31;
    const int nBase = blockIdx.x * BN;
    const int cBase = blockIdx.y * NCHS;

    // Warp tiling: 2 warps along M (32 rows), 4 warps along N (16 cols)
    const int wm = (warp & 1) * 32;
    const int wn = (warp >> 1) * 16;

    const int grp = lane >> 2;
    const int tq  = lane & 3;

    // x staging: thread -> (row, quarter), 4 x 16B cp.async
    const int xm = tid >> 2;
    const int xq = tid & 3;

    // weight staging: thread -> 4 contiguous qwords of one row
    const int wrow = tid >> 2;
    const int wseg = tid & 3;
    const int wo   = nBase + wrow;

    // ---- ldmatrix base addresses (buffer 0; add TILE_BYTES for buffer 1) ----
    const unsigned xs_base = (unsigned)__cvta_generic_to_shared(&xs[0][0][0]);
    const unsigned ws_base = (unsigned)__cvta_generic_to_shared(&ws[0][0][0]);
    const int arow = (((lane >> 3) & 1) << 3) + (lane & 7);
    const int acol = (lane >> 4) << 3;
    unsigned a_addr[2];
    #pragma unroll
    for (int mt = 0; mt < 2; mt++)
        a_addr[mt] = xs_base + ((wm + mt * 16 + arow) * XSTR + acol) * 2;
    const int brow = lane & 7;
    const int bcol = ((lane >> 3) & 1) << 3;
    unsigned b_addr[2];
    #pragma unroll
    for (int nt = 0; nt < 2; nt++)
        b_addr[nt] = ws_base + ((wn + nt * 8 + brow) * XSTR + bcol) * 2;

    float acc[2][2][4];
    #pragma unroll
    for (int i = 0; i < 2; i++)
        #pragma unroll
        for (int j = 0; j < 2; j++)
            #pragma unroll
            for (int r = 0; r < 4; r++) acc[i][j][r] = 0.0f;

    // ---- two-deep weight staging registers ----
    uint4    qr[2];
    unsigned s2r[2];
    unsigned mag2[2];

    auto cpasync_x = [&](int c, int buf) {
        const __half* src = g_xh + xm * K_TOT + c * BK + xq * 32;
        unsigned dst = (unsigned)__cvta_generic_to_shared(&xs[buf][xm][xq * 32]);
        #pragma unroll
        for (int j = 0; j < 4; j++)
            CP_ASYNC16(dst + j * 16, src + j * 8);
        CP_COMMIT();
    };

    auto load_w = [&](int c, int slot) {
        const int kb = c * BK;
        qr[slot] = *(const uint4*)(qw + wo * (K_TOT / 8) + (kb >> 3) + wseg * 4);
        unsigned zw = (unsigned)qz[wo * GPACK + (c >> 3)];
        unsigned z  = (zw >> ((c & 7) * 4)) & 15u;
        unsigned hm = 0x6400u + z;
        mag2[slot] = hm | (hm << 16);
        __half s = __float2half_rn(sc[wo * NGRP + c]);
        unsigned hs = (unsigned)__half_as_ushort(s);
        s2r[slot] = hs | (hs << 16);
    };

    auto store_w = [&](int slot, int buf) {
        const unsigned wv[4] = {qr[slot].x, qr[slot].y, qr[slot].z, qr[slot].w};
        const __half2 m2 = *(const __half2*)&mag2[slot];
        const __half2 s2 = *(const __half2*)&s2r[slot];
        #pragma unroll
        for (int j = 0; j < 4; j++) {
            unsigned w32 = wv[j];
            __half2 vals[4];
            #pragma unroll
            for (int p = 0; p < 4; p++) {
                unsigned t  = w32 >> (8 * p);
                unsigned h2 = (t & 0xFu) | ((t & 0xF0u) << 12) | 0x64006400u;
                vals[p] = __hmul2(__hsub2(*(const __half2*)&h2, m2), s2);
            }
            *(uint4*)(&ws[buf][wrow][(wseg * 4 + j) * 8]) = *(uint4*)vals;
        }
    };

    // ---- prologue: stage chunk 0, weight-prefetch chunk 1 ----
    cpasync_x(cBase, 0);
    load_w(cBase, 0);
    store_w(0, 0);                 // one-time LDG stall
    load_w(cBase + 1, 1);
    CP_WAIT0();

    #pragma unroll 2
    for (int i = 0; i < NCHS; i++) {
        __syncthreads();           // staging for chunk i complete, buffers (i-1)%2 free

        const int cur = i & 1;
        const int nxt = cur ^ 1;

        if (i + 1 < NCHS) cpasync_x(cBase + i + 1, nxt);   // full chunk of cover
        if (i + 2 < NCHS) load_w(cBase + i + 2, i & 1);    // 2-chunk LDG distance

        const unsigned boff = cur * (unsigned)TILE_BYTES;

        #pragma unroll
        for (int kk = 0; kk < BK; kk += 16) {
            unsigned a[2][4], b[2][2];
            #pragma unroll
            for (int mt = 0; mt < 2; mt++)
                LDSM_X4(a[mt][0], a[mt][1], a[mt][2], a[mt][3],
                        a_addr[mt] + boff + kk * 2);
            #pragma unroll
            for (int nt = 0; nt < 2; nt++)
                LDSM_X2(b[nt][0], b[nt][1], b_addr[nt] + boff + kk * 2);
            #pragma unroll
            for (int mt = 0; mt < 2; mt++)
                #pragma unroll
                for (int nt = 0; nt < 2; nt++)
                    asm volatile(
                        "mma.sync.aligned.m16n8k16.row.col.f32.f16.f16.f32 "
                        "{%0,%1,%2,%3}, {%4,%5,%6,%7}, {%8,%9}, {%0,%1,%2,%3};\n"
                        : "+f"(acc[mt][nt][0]), "+f"(acc[mt][nt][1]),
                          "+f"(acc[mt][nt][2]), "+f"(acc[mt][nt][3])
                        : "r"(a[mt][0]), "r"(a[mt][1]), "r"(a[mt][2]), "r"(a[mt][3]),
                          "r"(b[nt][0]), "r"(b[nt][1]));
        }

        if (i + 1 < NCHS) store_w((i + 1) & 1, nxt);   // weights issued 1 chunk ago
        CP_WAIT0();                                    // x(i+1) landed (covered by MMA)
    }

    // ---- epilogue: accumulate split partials ----
    #pragma unroll
    for (int mt = 0; mt < 2; mt++) {
        #pragma unroll
        for (int nt = 0; nt < 2; nt++) {
            int row = wm + mt * 16 + grp;
            int col = nBase + wn + nt * 8 + tq * 2;
            atomicAdd(&out[row * O_TOT + col],           acc[mt][nt][0]);
            atomicAdd(&out[row * O_TOT + col + 1],       acc[mt][nt][1]);
            atomicAdd(&out[(row + 8) * O_TOT + col],     acc[mt][nt][2]);
            atomicAdd(&out[(row + 8) * O_TOT + col + 1], acc[mt][nt][3]);
        }
    }
}

extern "C" void kernel_launch(void* const* d_in, const int* in_sizes, int n_in,
                              void* d_out, int out_size)
{
    const float* x  = (const float*)d_in[0];   // [64, 4096] (fp16 upcast to fp32)
    const int*   qw = (const int*)  d_in[1];   // [11008, 512] int32
    const int*   qz = (const int*)  d_in[2];   // [11008, 4]   int32
    const float* sc = (const float*)d_in[3];   // [11008, 32]  (fp16 upcast to fp32)
    float*       out = (float*)d_out;          // [64, 11008]  fp32

    cudaFuncSetAttribute(w4a16_mma_kernel,
                         cudaFuncAttributeMaxDynamicSharedMemorySize, SMEM_BYTES);

    prologue_kernel<<<(PRO_TOT + 511) / 512, 512>>>(x, out);

    dim3 grid(O_TOT / BN, KSPLIT);   // (172, 2)
    w4a16_mma_kernel<<<grid, NTHREADS, SMEM_BYTES>>>(qw, qz, sc, out);
}

// round 14
// speedup vs baseline: 1.2824x; 1.2824x over previous
#include <cuda_runtime.h>
#include <cuda_fp16.h>
#include <cstdint>

// Problem shape (fixed by the dataset)
#define M_TOT   64
#define K_TOT   4096
#define O_TOT   11008
#define GROUP   128
#define NGRP    (K_TOT / GROUP)        // 32
#define GPACK   ((NGRP + 7) / 8)       // 4

// Tiling
#define BN      128         // outputs per block (8 warps x 32x32 warp tiles)
#define BK      128         // K chunk = one quant group
#define KSPLIT  4           // grid (86, 4) = 344 blocks
#define NCHS    (K_TOT / BK / KSPLIT)  // 8 chunks per block
#define PADH    8
#define XSTR    (BK + PADH)            // 136 halfs row stride (272 B)
#define NTHREADS 256

#define XS_HALFS (M_TOT * XSTR)        // 8704
#define WS_HALFS (BN * XSTR)           // 17408
#define SMEM_BYTES ((XS_HALFS + WS_HALFS) * 2)   // 52224 B -> dynamic smem

// fp16 copy of x, produced once per launch
__device__ __half g_xh[M_TOT * K_TOT];

#define ZERO_F4   (M_TOT * O_TOT / 4)
#define CVT_F4    (M_TOT * K_TOT / 4)
#define PRO_TOT   (ZERO_F4 + CVT_F4)

__global__ __launch_bounds__(512) void prologue_kernel(const float* __restrict__ x,
                                                       float* __restrict__ out)
{
    int idx = blockIdx.x * blockDim.x + threadIdx.x;
    if (idx < ZERO_F4) {
        ((float4*)out)[idx] = make_float4(0.f, 0.f, 0.f, 0.f);
    } else if (idx < PRO_TOT) {
        int i = idx - ZERO_F4;
        float4 v = ((const float4*)x)[i];
        __half2* dst = (__half2*)g_xh;
        dst[i * 2]     = __floats2half2_rn(v.x, v.y);
        dst[i * 2 + 1] = __floats2half2_rn(v.z, v.w);
    }
}

#define CP_ASYNC16(dst_u32, src_ptr) \
    asm volatile("cp.async.cg.shared.global [%0], [%1], 16;\n" :: "r"(dst_u32), "l"(src_ptr))
#define CP_COMMIT() asm volatile("cp.async.commit_group;\n" ::: "memory")
#define CP_WAIT0()  asm volatile("cp.async.wait_group 0;\n" ::: "memory")

#define LDSM_X4(r0, r1, r2, r3, addr) \
    asm volatile("ldmatrix.sync.aligned.m8n8.x4.shared.b16 {%0,%1,%2,%3}, [%4];\n" \
                 : "=r"(r0), "=r"(r1), "=r"(r2), "=r"(r3) : "r"(addr))

__global__ __launch_bounds__(NTHREADS)
void w4a16_mma_kernel(const int*   __restrict__ qw,
                      const int*   __restrict__ qz,
                      const float* __restrict__ sc,
                      float*       __restrict__ out)
{
    extern __shared__ __half smem[];
    __half (*xs)[XSTR] = (__half (*)[XSTR])smem;               // [64][136]
    __half (*ws)[XSTR] = (__half (*)[XSTR])(smem + XS_HALFS);  // [128][136]

    const int tid  = threadIdx.x;
    const int warp = tid >> 5;
    const int lane = tid & 31;
    const int nBase = blockIdx.x * BN;
    const int cBase = blockIdx.y * NCHS;

    // Warp tiling: 2 warps along M (32 rows), 4 warps along N (32 cols each)
    const int wm = (warp & 1) * 32;
    const int wn = (warp >> 1) * 32;

    const int grp = lane >> 2;
    const int tq  = lane & 3;

    // x staging: thread -> (row, quarter), 4 x 16B cp.async
    const int xm = tid >> 2;
    const int xq = tid & 3;

    // weight staging: 2 threads per row, 8 qwords each (= 2 uint4)
    const int wrow = tid >> 1;               // 0..127
    const int wseg = tid & 1;                // 0..1
    const int wo   = nBase + wrow;

    // ---- ldmatrix addresses (per-lane, constant over chunks) ----
    const unsigned xs_base = (unsigned)__cvta_generic_to_shared(&xs[0][0]);
    const unsigned ws_base = (unsigned)__cvta_generic_to_shared(&ws[0][0]);
    // A x4: matrices (row0 k0),(row8 k0),(row0 k8),(row8 k8)
    const int arow = (((lane >> 3) & 1) << 3) + (lane & 7);
    const int acol = (lane >> 4) << 3;
    unsigned a_addr[2];
    #pragma unroll
    for (int mt = 0; mt < 2; mt++)
        a_addr[mt] = xs_base + ((wm + mt * 16 + arow) * XSTR + acol) * 2;
    // B x4 (per nt-pair): matrices (col0 k0),(col0 k8),(col8 k0),(col8 k8)
    const int brow = ((lane >> 4) << 3) + (lane & 7);
    const int bcol = ((lane >> 3) & 1) << 3;
    unsigned b_addr[2];
    #pragma unroll
    for (int np = 0; np < 2; np++)
        b_addr[np] = ws_base + ((wn + np * 16 + brow) * XSTR + bcol) * 2;

    float acc[2][4][4];
    #pragma unroll
    for (int i = 0; i < 2; i++)
        #pragma unroll
        for (int j = 0; j < 4; j++)
            #pragma unroll
            for (int r = 0; r < 4; r++) acc[i][j][r] = 0.0f;

    // ---- two-deep weight staging pipeline ----
    uint4    qr[2][2];
    unsigned s2r[2];
    unsigned mag2[2];

    auto cpasync_x = [&](int c) {
        const __half* src = g_xh + xm * K_TOT + c * BK + xq * 32;
        unsigned dst = (unsigned)__cvta_generic_to_shared(&xs[xm][xq * 32]);
        #pragma unroll
        for (int j = 0; j < 4; j++)
            CP_ASYNC16(dst + j * 16, src + j * 8);
        CP_COMMIT();
    };

    auto load_w = [&](int c, int slot) {
        const int kb = c * BK;
        const uint4* base = (const uint4*)(qw + wo * (K_TOT / 8) + (kb >> 3) + wseg * 8);
        qr[slot][0] = base[0];
        qr[slot][1] = base[1];
        unsigned zw = (unsigned)qz[wo * GPACK + (c >> 3)];
        unsigned z  = (zw >> ((c & 7) * 4)) & 15u;
        unsigned hm = 0x6400u + z;           // fp16 bits of (1024+z), exact
        mag2[slot] = hm | (hm << 16);
        __half s = __float2half_rn(sc[wo * NGRP + c]);
        unsigned hs = (unsigned)__half_as_ushort(s);
        s2r[slot] = hs | (hs << 16);
    };

    auto store_w = [&](int slot) {
        const __half2 m2 = *(const __half2*)&mag2[slot];
        const __half2 s2 = *(const __half2*)&s2r[slot];
        #pragma unroll
        for (int u = 0; u < 2; u++) {
            const unsigned wv[4] = {qr[slot][u].x, qr[slot][u].y,
                                    qr[slot][u].z, qr[slot][u].w};
            #pragma unroll
            for (int j = 0; j < 4; j++) {
                unsigned w32 = wv[j];
                __half2 vals[4];
                #pragma unroll
                for (int p = 0; p < 4; p++) {
                    unsigned t  = w32 >> (8 * p);
                    unsigned h2 = (t & 0xFu) | ((t & 0xF0u) << 12) | 0x64006400u;
                    vals[p] = __hmul2(__hsub2(*(const __half2*)&h2, m2), s2);
                }
                *(uint4*)(&ws[wrow][(wseg * 8 + u * 4 + j) * 8]) = *(uint4*)vals;
            }
        }
    };

    // ---- prologue: stage chunk 0, weight-prefetch chunk 1 ----
    cpasync_x(cBase);
    load_w(cBase, 0);
    store_w(0);                    // one-time LDG stall
    load_w(cBase + 1, 1);
    CP_WAIT0();

    #pragma unroll
    for (int i = 0; i < NCHS; i++) {
        __syncthreads();                     // tile i (xs + ws) ready

        // issue chunk i+2 weight LDGs now -> consumed at iter i+1 tail
        if (i + 2 < NCHS) load_w(cBase + i + 2, i & 1);

        #pragma unroll
        for (int kk = 0; kk < BK; kk += 16) {
            unsigned a[2][4], b[4][2];
            #pragma unroll
            for (int mt = 0; mt < 2; mt++)
                LDSM_X4(a[mt][0], a[mt][1], a[mt][2], a[mt][3], a_addr[mt] + kk * 2);
            #pragma unroll
            for (int np = 0; np < 2; np++)
                LDSM_X4(b[np * 2][0], b[np * 2][1], b[np * 2 + 1][0], b[np * 2 + 1][1],
                        b_addr[np] + kk * 2);
            #pragma unroll
            for (int mt = 0; mt < 2; mt++)
                #pragma unroll
                for (int nt = 0; nt < 4; nt++)
                    asm volatile(
                        "mma.sync.aligned.m16n8k16.row.col.f32.f16.f16.f32 "
                        "{%0,%1,%2,%3}, {%4,%5,%6,%7}, {%8,%9}, {%0,%1,%2,%3};\n"
                        : "+f"(acc[mt][nt][0]), "+f"(acc[mt][nt][1]),
                          "+f"(acc[mt][nt][2]), "+f"(acc[mt][nt][3])
                        : "r"(a[mt][0]), "r"(a[mt][1]), "r"(a[mt][2]), "r"(a[mt][3]),
                          "r"(b[nt][0]), "r"(b[nt][1]));
        }

        __syncthreads();                     // all warps done reading tile i

        if (i + 1 < NCHS) {
            cpasync_x(cBase + i + 1);        // async x refill (L2-resident)
            store_w((i + 1) & 1);            // weights issued a full chunk ago
            CP_WAIT0();
        }
    }

    // ---- epilogue: accumulate split partials ----
    #pragma unroll
    for (int mt = 0; mt < 2; mt++) {
        #pragma unroll
        for (int nt = 0; nt < 4; nt++) {
            int row = wm + mt * 16 + grp;
            int col = nBase + wn + nt * 8 + tq * 2;
            atomicAdd(&out[row * O_TOT + col],           acc[mt][nt][0]);
            atomicAdd(&out[row * O_TOT + col + 1],       acc[mt][nt][1]);
            atomicAdd(&out[(row + 8) * O_TOT + col],     acc[mt][nt][2]);
            atomicAdd(&out[(row + 8) * O_TOT + col + 1], acc[mt][nt][3]);
        }
    }
}

extern "C" void kernel_launch(void* const* d_in, const int* in_sizes, int n_in,
                              void* d_out, int out_size)
{
    const float* x  = (const float*)d_in[0];   // [64, 4096] (fp16 upcast to fp32)
    const int*   qw = (const int*)  d_in[1];   // [11008, 512] int32
    const int*   qz = (const int*)  d_in[2];   // [11008, 4]   int32
    const float* sc = (const float*)d_in[3];   // [11008, 32]  (fp16 upcast to fp32)
    float*       out = (float*)d_out;          // [64, 11008]  fp32

    cudaFuncSetAttribute(w4a16_mma_kernel,
                         cudaFuncAttributeMaxDynamicSharedMemorySize, SMEM_BYTES);

    prologue_kernel<<<(PRO_TOT + 511) / 512, 512>>>(x, out);

    dim3 grid(O_TOT / BN, KSPLIT);   // (86, 4)
    w4a16_mma_kernel<<<grid, NTHREADS, SMEM_BYTES>>>(qw, qz, sc, out);
}